// round 9
// baseline (speedup 1.0000x reference)
#include <cuda_runtime.h>
#include <cuda_bf16.h>
#include <cstdint>

// Problem constants
#define BB 4
#define LL 1024
#define DD 768
#define HH 12
#define KW 384            // K/2 packed words (K = 768)
#define QKVW 1152         // 2304/2 words per qkv row
#define OW 384            // 768/2 words per attn-out row
#define AS 36             // attn smem stride (words)
#define GS 20             // gemm smem stride (words), conflict-free quads

// Scratch (device globals; no cudaMalloc allowed)
__device__ __align__(16) uint32_t g_xh[4096 * KW],  g_xl[4096 * KW];
__device__ __align__(16) uint32_t g_wih[2304 * KW], g_wil[2304 * KW];
__device__ __align__(16) uint32_t g_woh[768 * KW],  g_wol[768 * KW];
__device__ __align__(16) uint32_t g_qh[4096 * QKVW], g_ql[4096 * QKVW];
__device__ __align__(16) uint32_t g_oh[4096 * OW],   g_ol[4096 * OW];

// ---------------------------------------------------------------------------
// helpers
// ---------------------------------------------------------------------------
__device__ __forceinline__ uint32_t pack2(float e0, float e1) {
    uint32_t d;  // low half = e0, high half = e1
    asm("cvt.rn.bf16x2.f32 %0, %1, %2;" : "=r"(d) : "f"(e1), "f"(e0));
    return d;
}
__device__ __forceinline__ void split2(float e0, float e1, uint32_t& h, uint32_t& l) {
    h = pack2(e0, e1);
    float h0 = __uint_as_float(h << 16);
    float h1 = __uint_as_float(h & 0xffff0000u);
    l = pack2(e0 - h0, e1 - h1);
}
__device__ __forceinline__ void mma_bf16(float c[4], const uint32_t a[4],
                                         const uint32_t b[2]) {
    asm volatile(
        "mma.sync.aligned.m16n8k16.row.col.f32.bf16.bf16.f32 "
        "{%0,%1,%2,%3}, {%4,%5,%6,%7}, {%8,%9}, {%0,%1,%2,%3};"
        : "+f"(c[0]), "+f"(c[1]), "+f"(c[2]), "+f"(c[3])
        : "r"(a[0]), "r"(a[1]), "r"(a[2]), "r"(a[3]), "r"(b[0]), "r"(b[1]));
}
__device__ __forceinline__ uint32_t sptr(const void* p) {
    return (uint32_t)__cvta_generic_to_shared(p);
}
__device__ __forceinline__ void cpa16(uint32_t s, const void* g) {
    asm volatile("cp.async.ca.shared.global [%0], [%1], 16;" :: "r"(s), "l"(g));
}
__device__ __forceinline__ void cp_commit() {
    asm volatile("cp.async.commit_group;" ::: "memory");
}
__device__ __forceinline__ void cp_wait1() {
    asm volatile("cp.async.wait_group 1;" ::: "memory");
}
__device__ __forceinline__ void cp_wait0() {
    asm volatile("cp.async.wait_group 0;" ::: "memory");
}
__device__ __forceinline__ void ldmx2t(uint32_t& r0, uint32_t& r1, uint32_t a) {
    asm volatile("ldmatrix.sync.aligned.m8n8.x2.trans.shared.b16 {%0,%1}, [%2];"
                 : "=r"(r0), "=r"(r1) : "r"(a));
}

// ---------------------------------------------------------------------------
// prepass: float -> packed bf16 hi/lo words
// ---------------------------------------------------------------------------
__global__ void splitpack_kernel(const float* __restrict__ in,
                                 uint32_t* __restrict__ h, uint32_t* __restrict__ l,
                                 int nw)
{
    int i = blockIdx.x * 256 + threadIdx.x;
    if (i < nw) {
        float2 v = ((const float2*)in)[i];
        uint32_t hh, ll;
        split2(v.x, v.y, hh, ll);
        h[i] = hh;
        l[i] = ll;
    }
}

// ---------------------------------------------------------------------------
// GEMM: C[M,N] = A[M,768] @ W[N,768]^T + bias[N], bf16 split x3 mma.sync.
// CTA 128x128, 256 thr = 8 warps arranged 2(m) x 2(n) x 2(k-split).
// Warp tile 64x64 (4 m16 x 8 n8), each warp covers half the K range:
// iter covers 16 k-words (32 bf16 K); warp wk takes words [wk*8, wk*8+8).
// 2-stage cp.async ring (Ah|Al|Bh|Bl per stage, stride GS). Epilogue reduces
// the two k-halves through smem, adds bias, stores (packed or float).
// ---------------------------------------------------------------------------
template<bool PACKED_OUT>
__global__ __launch_bounds__(256) void gemm_ksplit(
    const uint32_t* __restrict__ Agh, const uint32_t* __restrict__ Agl,
    const uint32_t* __restrict__ Wgh, const uint32_t* __restrict__ Wgl,
    const float* __restrict__ bias,
    float* __restrict__ Cf, uint32_t* __restrict__ Ch, uint32_t* __restrict__ Cl,
    int N, int scale_blocks)
{
    extern __shared__ uint32_t sm[];
    const int tid = threadIdx.x;
    const int lane = tid & 31, warp = tid >> 5;
    const int gid = lane >> 2, tig = lane & 3;
    const int wk = warp >> 2, wm = (warp >> 1) & 1, wn = warp & 1;
    const int m0 = blockIdx.y * 128, n0 = blockIdx.x * 128;
    const uint32_t smb = sptr(sm);
    const int SLOTW = 4 * 128 * GS;           // words per stage (10240)

    auto load = [&](int it) {
        if (it < 24) {
            const int kw = it * 16;
            const uint32_t sb = smb + (uint32_t)(it & 1) * SLOTW * 4;
#pragma unroll
            for (int j = 0; j < 2; j++) {
                const int c = tid + j * 256;        // 0..511
                const int row = c >> 2, wg = (c & 3) * 4;
                const uint32_t off = (uint32_t)(row * GS + wg) * 4;
                const size_t ga = (size_t)(m0 + row) * KW + kw + wg;
                const size_t gb = (size_t)(n0 + row) * KW + kw + wg;
                cpa16(sb + off, Agh + ga);
                cpa16(sb + 128 * GS * 4 + off, Agl + ga);
                cpa16(sb + 2 * 128 * GS * 4 + off, Wgh + gb);
                cpa16(sb + 3 * 128 * GS * 4 + off, Wgl + gb);
            }
        }
        cp_commit();   // empty groups keep wait bookkeeping uniform
    };

    float acc[4][8][4];
#pragma unroll
    for (int mt = 0; mt < 4; mt++)
#pragma unroll
        for (int nt = 0; nt < 8; nt++)
#pragma unroll
            for (int j = 0; j < 4; j++) acc[mt][nt][j] = 0.0f;

    load(0); load(1);

    const int wo = wk * 8;
    for (int it = 0; it < 24; it++) {
        cp_wait1();
        __syncthreads();
        const uint32_t* Ah = sm + (it & 1) * SLOTW;
        const uint32_t* Al = Ah + 128 * GS;
        const uint32_t* Bh = Ah + 2 * 128 * GS;
        const uint32_t* Bl = Ah + 3 * 128 * GS;

        uint32_t ah[4][4], al[4][4];
#pragma unroll
        for (int mt = 0; mt < 4; mt++) {
            const int r = wm * 64 + mt * 16 + gid;
            ah[mt][0] = Ah[r * GS + wo + tig];
            ah[mt][1] = Ah[(r + 8) * GS + wo + tig];
            ah[mt][2] = Ah[r * GS + wo + tig + 4];
            ah[mt][3] = Ah[(r + 8) * GS + wo + tig + 4];
            al[mt][0] = Al[r * GS + wo + tig];
            al[mt][1] = Al[(r + 8) * GS + wo + tig];
            al[mt][2] = Al[r * GS + wo + tig + 4];
            al[mt][3] = Al[(r + 8) * GS + wo + tig + 4];
        }
#pragma unroll
        for (int nt = 0; nt < 8; nt++) {
            const int n = wn * 64 + nt * 8 + gid;
            uint32_t bh[2] = {Bh[n * GS + wo + tig], Bh[n * GS + wo + tig + 4]};
            uint32_t bl[2] = {Bl[n * GS + wo + tig], Bl[n * GS + wo + tig + 4]};
#pragma unroll
            for (int mt = 0; mt < 4; mt++) {
                mma_bf16(acc[mt][nt], al[mt], bh);
                mma_bf16(acc[mt][nt], ah[mt], bl);
                mma_bf16(acc[mt][nt], ah[mt], bh);
            }
        }
        __syncthreads();
        load(it + 2);
    }

    // ---- k-split reduction via smem (layout idx*32+lane: conflict-free) ----
    cp_wait0();
    __syncthreads();
    float* slab = (float*)sm;                 // 4 pairs x 4096 floats = 64KB
    const int p = wm * 2 + wn;
    if (wk == 1) {
        float* dst = slab + p * 4096 + lane;
        const float* a = &acc[0][0][0];
#pragma unroll
        for (int i = 0; i < 128; i++) dst[i * 32] = a[i];
    }
    __syncthreads();
    if (wk == 0) {
        const float* src = slab + p * 4096 + lane;
        float* a = &acc[0][0][0];
#pragma unroll
        for (int i = 0; i < 128; i++) a[i] += src[i * 32];

        const float scl = (blockIdx.x < scale_blocks) ? 0.125f : 1.0f;
#pragma unroll
        for (int mt = 0; mt < 4; mt++) {
#pragma unroll
            for (int nt = 0; nt < 8; nt++) {
                const int n = n0 + wn * 64 + nt * 8 + tig * 2;
                const float2 bs = *(const float2*)(bias + n);
                const int r = m0 + wm * 64 + mt * 16 + gid;
                const float v0 = (acc[mt][nt][0] + bs.x) * scl;
                const float v1 = (acc[mt][nt][1] + bs.y) * scl;
                const float v2 = (acc[mt][nt][2] + bs.x) * scl;
                const float v3 = (acc[mt][nt][3] + bs.y) * scl;
                if (PACKED_OUT) {
                    uint32_t hh, ll;
                    size_t w = (size_t)r * (N / 2) + n / 2;
                    split2(v0, v1, hh, ll);
                    Ch[w] = hh; Cl[w] = ll;
                    w = (size_t)(r + 8) * (N / 2) + n / 2;
                    split2(v2, v3, hh, ll);
                    Ch[w] = hh; Cl[w] = ll;
                } else {
                    *(float2*)(Cf + (size_t)r * N + n) = make_float2(v0, v1);
                    *(float2*)(Cf + (size_t)(r + 8) * N + n) = make_float2(v2, v3);
                }
            }
        }
    }
}

// ---------------------------------------------------------------------------
// Flash attention, bf16 split x3 mma.sync, BQ=128 (8 warps), packed qkv in/out.
// Q frags in registers; K/V 2-stage cp.async; P stays in registers;
// V via ldmatrix.x2.trans.
// ---------------------------------------------------------------------------
__global__ __launch_bounds__(256) void attn_bf16(
    const uint32_t* __restrict__ Qh, const uint32_t* __restrict__ Ql,
    const float* __restrict__ bias,
    uint32_t* __restrict__ Oh, uint32_t* __restrict__ Ol)
{
    extern __shared__ uint32_t sma[];
    uint32_t* sKh = sma;                    // [2][64][AS]
    uint32_t* sKl = sma + 2 * 64 * AS;
    uint32_t* sVh = sma + 4 * 64 * AS;
    uint32_t* sVl = sma + 6 * 64 * AS;

    const int tid = threadIdx.x;
    const int lane = tid & 31, warp = tid >> 5;
    const int gid = lane >> 2, tig = lane & 3;
    const int qt = blockIdx.x, h = blockIdx.y, b = blockIdx.z;
    const int q0 = qt * 128, wq = warp * 16;

    const uint32_t sKh_b = sptr(sKh), sKl_b = sptr(sKl);
    const uint32_t sVh_b = sptr(sVh), sVl_b = sptr(sVl);

    const int kwbase = DD / 2 + h * 32;
    const int vwbase = DD + h * 32;
    const size_t tok0 = (size_t)b * LL;

    auto issue = [&](int st, int kt) {
#pragma unroll
        for (int i = 0; i < 2; i++) {
            const int c = tid + i * 256;           // 0..511
            const int row = c >> 3, wg = (c & 7) * 4;
            const uint32_t so = (uint32_t)((st * 64 + row) * AS + wg) * 4;
            const size_t g = (tok0 + kt * 64 + row) * QKVW + wg;
            cpa16(sKh_b + so, Qh + g + kwbase);
            cpa16(sKl_b + so, Ql + g + kwbase);
            cpa16(sVh_b + so, Qh + g + vwbase);
            cpa16(sVl_b + so, Ql + g + vwbase);
        }
        cp_commit();
    };

    // ---- Q fragments (already scaled in packed qkv) ----
    uint32_t qh[4][4], ql[4][4];
    {
        const uint32_t* r0h = Qh + (tok0 + q0 + wq + gid) * QKVW + h * 32;
        const uint32_t* r1h = r0h + 8 * QKVW;
        const uint32_t* r0l = Ql + (tok0 + q0 + wq + gid) * QKVW + h * 32;
        const uint32_t* r1l = r0l + 8 * QKVW;
#pragma unroll
        for (int ks = 0; ks < 4; ks++) {
            const int kw = ks * 8;
            qh[ks][0] = r0h[kw + tig];     qh[ks][1] = r1h[kw + tig];
            qh[ks][2] = r0h[kw + tig + 4]; qh[ks][3] = r1h[kw + tig + 4];
            ql[ks][0] = r0l[kw + tig];     ql[ks][1] = r1l[kw + tig];
            ql[ks][2] = r0l[kw + tig + 4]; ql[ks][3] = r1l[kw + tig + 4];
        }
    }

    float o[8][4];
#pragma unroll
    for (int dt = 0; dt < 8; dt++)
#pragma unroll
        for (int j = 0; j < 4; j++) o[dt][j] = 0.0f;
    float mr0 = -1e30f, mr1 = -1e30f, lr0 = 0.0f, lr1 = 0.0f;

    const float* bb = bias + ((size_t)(b * HH + h) * LL + q0 + wq) * LL;

    issue(0, 0);

    for (int kt = 0; kt < 16; kt++) {
        if (kt < 15) issue((kt + 1) & 1, kt + 1);
        if (kt < 15) cp_wait1(); else cp_wait0();
        __syncthreads();
        const int st = kt & 1;

        // ---- S = bias ----
        float s[8][4];
#pragma unroll
        for (int nt = 0; nt < 8; nt++) {
            const float* bp = bb + (size_t)gid * LL + kt * 64 + nt * 8 + tig * 2;
            float2 x0 = *(const float2*)bp;
            float2 x1 = *(const float2*)(bp + (size_t)8 * LL);
            s[nt][0] = x0.x; s[nt][1] = x0.y;
            s[nt][2] = x1.x; s[nt][3] = x1.y;
        }

        // ---- S += Q @ K^T ----
#pragma unroll
        for (int ks = 0; ks < 4; ks++) {
            const int kw = ks * 8;
#pragma unroll
            for (int nt = 0; nt < 8; nt++) {
                const uint32_t* ph = &sKh[(st * 64 + nt * 8 + gid) * AS];
                const uint32_t* pl = &sKl[(st * 64 + nt * 8 + gid) * AS];
                uint32_t bh[2] = {ph[kw + tig], ph[kw + tig + 4]};
                uint32_t bl[2] = {pl[kw + tig], pl[kw + tig + 4]};
                mma_bf16(s[nt], ql[ks], bh);
                mma_bf16(s[nt], qh[ks], bl);
                mma_bf16(s[nt], qh[ks], bh);
            }
        }

        // ---- online softmax (rows gid / gid+8) ----
        float mx0 = -1e30f, mx1 = -1e30f;
#pragma unroll
        for (int nt = 0; nt < 8; nt++) {
            mx0 = fmaxf(mx0, fmaxf(s[nt][0], s[nt][1]));
            mx1 = fmaxf(mx1, fmaxf(s[nt][2], s[nt][3]));
        }
        mx0 = fmaxf(mx0, __shfl_xor_sync(0xffffffffu, mx0, 1));
        mx0 = fmaxf(mx0, __shfl_xor_sync(0xffffffffu, mx0, 2));
        mx1 = fmaxf(mx1, __shfl_xor_sync(0xffffffffu, mx1, 1));
        mx1 = fmaxf(mx1, __shfl_xor_sync(0xffffffffu, mx1, 2));
        const float mn0 = fmaxf(mr0, mx0), mn1 = fmaxf(mr1, mx1);
        const float c0 = __expf(mr0 - mn0), c1 = __expf(mr1 - mn1);
        mr0 = mn0; mr1 = mn1;
        float ls0 = 0.0f, ls1 = 0.0f;
#pragma unroll
        for (int nt = 0; nt < 8; nt++) {
            s[nt][0] = __expf(s[nt][0] - mn0);
            s[nt][1] = __expf(s[nt][1] - mn0);
            s[nt][2] = __expf(s[nt][2] - mn1);
            s[nt][3] = __expf(s[nt][3] - mn1);
            ls0 += s[nt][0] + s[nt][1];
            ls1 += s[nt][2] + s[nt][3];
        }
        ls0 += __shfl_xor_sync(0xffffffffu, ls0, 1);
        ls0 += __shfl_xor_sync(0xffffffffu, ls0, 2);
        ls1 += __shfl_xor_sync(0xffffffffu, ls1, 1);
        ls1 += __shfl_xor_sync(0xffffffffu, ls1, 2);
        lr0 = lr0 * c0 + ls0;
        lr1 = lr1 * c1 + ls1;
#pragma unroll
        for (int dt = 0; dt < 8; dt++) {
            o[dt][0] *= c0; o[dt][1] *= c0;
            o[dt][2] *= c1; o[dt][3] *= c1;
        }

        // ---- O += P @ V ----
#pragma unroll
        for (int ks = 0; ks < 4; ks++) {
            uint32_t ph[4], pl[4];
            split2(s[2 * ks][0],     s[2 * ks][1],     ph[0], pl[0]);
            split2(s[2 * ks][2],     s[2 * ks][3],     ph[1], pl[1]);
            split2(s[2 * ks + 1][0], s[2 * ks + 1][1], ph[2], pl[2]);
            split2(s[2 * ks + 1][2], s[2 * ks + 1][3], ph[3], pl[3]);
            const uint32_t rowoff =
                (uint32_t)((st * 64 + 16 * ks + (lane & 15)) * AS) * 4;
#pragma unroll
            for (int dt = 0; dt < 8; dt++) {
                uint32_t vh2[2], vl2[2];
                ldmx2t(vh2[0], vh2[1], sVh_b + rowoff + dt * 16);
                ldmx2t(vl2[0], vl2[1], sVl_b + rowoff + dt * 16);
                mma_bf16(o[dt], pl, vh2);
                mma_bf16(o[dt], ph, vl2);
                mma_bf16(o[dt], ph, vh2);
            }
        }
        __syncthreads();
    }

    // ---- normalize + packed store ----
    const float inv0 = 1.0f / lr0, inv1 = 1.0f / lr1;
#pragma unroll
    for (int dt = 0; dt < 8; dt++) {
        uint32_t hh, ll;
        size_t w = (tok0 + q0 + wq + gid) * OW + h * 32 + dt * 4 + tig;
        split2(o[dt][0] * inv0, o[dt][1] * inv0, hh, ll);
        Oh[w] = hh; Ol[w] = ll;
        w = (tok0 + q0 + wq + 8 + gid) * OW + h * 32 + dt * 4 + tig;
        split2(o[dt][2] * inv1, o[dt][3] * inv1, hh, ll);
        Oh[w] = hh; Ol[w] = ll;
    }
}

// ---------------------------------------------------------------------------
// Launch
// ---------------------------------------------------------------------------
extern "C" void kernel_launch(void* const* d_in, const int* in_sizes, int n_in,
                              void* d_out, int out_size)
{
    const float* x         = (const float*)d_in[0];   // [B, L, D]
    const float* attn_bias = (const float*)d_in[1];   // [B, H, L, L]
    const float* w_in      = (const float*)d_in[2];   // [3D, D]
    const float* b_in      = (const float*)d_in[3];   // [3D]
    const float* w_out     = (const float*)d_in[4];   // [D, D]
    const float* b_out     = (const float*)d_in[5];   // [D]
    float* out = (float*)d_out;                       // [B, L, D]

    uint32_t *xh, *xl, *wih, *wil, *woh, *wol, *qh, *ql, *oh, *ol;
    cudaGetSymbolAddress((void**)&xh,  g_xh);  cudaGetSymbolAddress((void**)&xl,  g_xl);
    cudaGetSymbolAddress((void**)&wih, g_wih); cudaGetSymbolAddress((void**)&wil, g_wil);
    cudaGetSymbolAddress((void**)&woh, g_woh); cudaGetSymbolAddress((void**)&wol, g_wol);
    cudaGetSymbolAddress((void**)&qh,  g_qh);  cudaGetSymbolAddress((void**)&ql,  g_ql);
    cudaGetSymbolAddress((void**)&oh,  g_oh);  cudaGetSymbolAddress((void**)&ol,  g_ol);

    // 0) split-pack prepass
    {
        const int nx = 4096 * KW, nwi = 2304 * KW, nwo = 768 * KW;
        splitpack_kernel<<<(nx + 255) / 256, 256>>>(x, xh, xl, nx);
        splitpack_kernel<<<(nwi + 255) / 256, 256>>>(w_in, wih, wil, nwi);
        splitpack_kernel<<<(nwo + 255) / 256, 256>>>(w_out, woh, wol, nwo);
    }

    const int gemm_smem = 2 * 4 * 128 * GS * 4;   // 81920 B
    const int attn_smem = 8 * 64 * AS * 4;        // 73728 B

    // 1) QKV projection -> packed hi/lo, q pre-scaled by 0.125 (blocks 0..5)
    {
        cudaFuncSetAttribute(gemm_ksplit<true>,
                             cudaFuncAttributeMaxDynamicSharedMemorySize, gemm_smem);
        dim3 grid(2304 / 128, 4096 / 128);
        gemm_ksplit<true><<<grid, 256, gemm_smem>>>(
            xh, xl, wih, wil, b_in, nullptr, qh, ql, 2304, 6);
    }

    // 2) attention -> packed hi/lo
    {
        cudaFuncSetAttribute(attn_bf16,
                             cudaFuncAttributeMaxDynamicSharedMemorySize, attn_smem);
        dim3 grid(LL / 128, HH, BB);
        attn_bf16<<<grid, 256, attn_smem>>>(qh, ql, attn_bias, oh, ol);
    }

    // 3) output projection -> float out
    {
        cudaFuncSetAttribute(gemm_ksplit<false>,
                             cudaFuncAttributeMaxDynamicSharedMemorySize, gemm_smem);
        dim3 grid(768 / 128, 4096 / 128);
        gemm_ksplit<false><<<grid, 256, gemm_smem>>>(
            oh, ol, woh, wol, b_out, out, nullptr, nullptr, 768, 0);
    }
}